// round 8
// baseline (speedup 1.0000x reference)
#include <cuda_runtime.h>
#include <math.h>

#define NPIX 4096
#define BATCH 8
#define CH 64
#define KSPLIT 4

typedef unsigned long long u64;

// ---------------- f32x2 helpers (Blackwell packed fp32) ----------------
__device__ __forceinline__ u64 pk2(float lo, float hi) {
    u64 r; asm("mov.b64 %0, {%1, %2};" : "=l"(r) : "f"(lo), "f"(hi)); return r;
}
__device__ __forceinline__ void upk2(u64 v, float& lo, float& hi) {
    asm("mov.b64 {%0, %1}, %2;" : "=f"(lo), "=f"(hi) : "l"(v));
}
__device__ __forceinline__ u64 ffma2(u64 a, u64 b, u64 c) {
    u64 d; asm("fma.rn.f32x2 %0, %1, %2, %3;" : "=l"(d) : "l"(a), "l"(b), "l"(c)); return d;
}
union V4 { float4 f; u64 u[2]; };
union F2 { float2 f; u64 u; };

// ---------------- scratch (device globals) ----------------
__device__ float g_featB[BATCH * 8 * NPIX];
__device__ float g_featC[BATCH * 8 * NPIX];
__device__ float g_featD[BATCH * CH * NPIX];
__device__ float g_featDT[BATCH * NPIX * CH];       // key-major V
__device__ float g_pacc[KSPLIT * BATCH * CH * NPIX]; // split-K partial numerators
__device__ float g_pssum[KSPLIT * BATCH * NPIX];     // split-K partial denominators
__device__ float g_scale[BATCH * NPIX];              // alpha / total denominator
__device__ float g_xa[BATCH * CH * NPIX];
__device__ float g_xb[BATCH * CH * NPIX];
__device__ float g_attPart[16 * BATCH * CH * CH];
__device__ float g_attW[BATCH * CH * CH];
__device__ float g_conv[BATCH * 128 * NPIX];
__device__ float g_bnScale[128];
__device__ float g_bnShift[128];
__device__ float2 g_cw2[128 * 576];                  // duplicated conv weights

// ---------------- K1: fused 1x1 projections ----------------
__global__ void k1_proj(const float* __restrict__ x,
                        const float* __restrict__ wb, const float* __restrict__ bb,
                        const float* __restrict__ wc, const float* __restrict__ bc,
                        const float* __restrict__ wd, const float* __restrict__ bd) {
    __shared__ float Ws[16][64];
    __shared__ float Bs[16];
    const int t = threadIdx.x;
    const int og0 = blockIdx.y * 16;
    const int b = blockIdx.z;

    for (int i = t; i < 16 * 64; i += 256) {
        int o = og0 + (i >> 6), c = i & 63;
        float w;
        if (o < 8) w = wb[o * 64 + c];
        else if (o < 16) w = wc[(o - 8) * 64 + c];
        else w = wd[(o - 16) * 64 + c];
        Ws[i >> 6][c] = w;
    }
    if (t < 16) {
        int o = og0 + t;
        Bs[t] = (o < 8) ? bb[o] : (o < 16) ? bc[o - 8] : bd[o - 16];
    }
    __syncthreads();

    const int n = blockIdx.x * 256 + t;
    const float* xp = x + (size_t)b * CH * NPIX + n;
    float acc[16];
#pragma unroll
    for (int i = 0; i < 16; i++) acc[i] = Bs[i];

    for (int c = 0; c < 64; c += 4) {
        float x0 = xp[(size_t)(c + 0) * NPIX];
        float x1 = xp[(size_t)(c + 1) * NPIX];
        float x2 = xp[(size_t)(c + 2) * NPIX];
        float x3 = xp[(size_t)(c + 3) * NPIX];
#pragma unroll
        for (int o = 0; o < 16; o++) {
            float4 w = *(const float4*)&Ws[o][c];
            acc[o] = fmaf(w.x, x0, fmaf(w.y, x1, fmaf(w.z, x2, fmaf(w.w, x3, acc[o]))));
        }
    }
#pragma unroll
    for (int o = 0; o < 16; o++) {
        int og = og0 + o;
        if (og < 8)       g_featB[(size_t)(b * 8 + og) * NPIX + n] = acc[o];
        else if (og < 16) g_featC[(size_t)(b * 8 + og - 8) * NPIX + n] = acc[o];
        else              g_featD[(size_t)(b * CH + og - 16) * NPIX + n] = acc[o];
    }
}

// ---------------- K1t: transpose featD [b][c][n] -> featDT [b][n][c] ----------------
__global__ void k1t_transpose() {
    __shared__ float tile[64][65];
    const int t = threadIdx.x;
    const int b = blockIdx.y;
    const int n0 = blockIdx.x * 64;
#pragma unroll
    for (int k = 0; k < 16; k++) {
        int i = t + 256 * k;
        int c = i >> 6, nn = i & 63;
        tile[c][nn] = g_featD[(size_t)(b * CH + c) * NPIX + n0 + nn];
    }
    __syncthreads();
#pragma unroll
    for (int k = 0; k < 16; k++) {
        int i = t + 256 * k;
        int nn = i >> 6, c = i & 63;
        g_featDT[((size_t)b * NPIX + n0 + nn) * CH + c] = tile[c][nn];
    }
}

// ---------------- K2: PAM flash attention, split-K partials ----------------
// grid (32 qtiles, KSPLIT, 8 batch), block 128, max 128 regs (4 CTAs/SM).
// Thread = (query pair, channel half); K values read inline (no Kq buffer).
__global__ void __launch_bounds__(128, 4) k2_pam() {
    __shared__ float Ks[8][128];    // [dim][key]
    __shared__ float Vs[128][64];   // [key][channel]
    const int t = threadIdx.x;
    const int ks = blockIdx.y;
    const int b = blockIdx.z;
    const int n0 = blockIdx.x * 128;
    const int qi = t & 63;          // query pair index
    const int chalf = t >> 6;       // channel half
    const int nq = n0 + qi * 2;

    u64 q2[8];
#pragma unroll
    for (int d = 0; d < 8; d++) {
        const float* fp = g_featB + (size_t)(b * 8 + d) * NPIX + nq;
        q2[d] = pk2(fp[0], fp[1]);
    }

    u64 acc0[16], acc1[16];
#pragma unroll
    for (int i = 0; i < 16; i++) { acc0[i] = 0ull; acc1[i] = 0ull; }
    float ssum0 = 0.f, ssum1 = 0.f;

    const float4* fc4 = (const float4*)(g_featC + (size_t)b * 8 * NPIX);
    const float4* fdt4 = (const float4*)(g_featDT + (size_t)b * NPIX * CH);

    const int mc0 = ks * (32 / KSPLIT);
    for (int mc = mc0; mc < mc0 + 32 / KSPLIT; mc++) {
        const int m04 = mc * 32;
        const int m0 = mc * 128;
#pragma unroll
        for (int k = 0; k < 2; k++) {  // K tile
            int i = t + 128 * k;
            int d = i >> 5, col = i & 31;
            ((float4*)Ks[d])[col] = fc4[d * 1024 + m04 + col];
        }
#pragma unroll
        for (int k = 0; k < 16; k++) { // V tile
            int i = t + 128 * k;
            int row = i >> 4, cq = i & 15;
            ((float4*)Vs[row])[cq] = fdt4[(size_t)(m0 + row) * 16 + cq];
        }
        __syncthreads();

        for (int g = 0; g < 32; g++) {
            u64 lp[4] = {0ull, 0ull, 0ull, 0ull};
#pragma unroll
            for (int d = 0; d < 8; d++) {
                float4 kv = ((const float4*)Ks[d])[g];   // inline, short-lived
                lp[0] = ffma2(q2[d], pk2(kv.x, kv.x), lp[0]);
                lp[1] = ffma2(q2[d], pk2(kv.y, kv.y), lp[1]);
                lp[2] = ffma2(q2[d], pk2(kv.z, kv.z), lp[2]);
                lp[3] = ffma2(q2[d], pk2(kv.w, kv.w), lp[3]);
            }
#pragma unroll
            for (int j = 0; j < 4; j++) {
                float l0, l1;
                upk2(lp[j], l0, l1);
                float p0 = __expf(l0), p1 = __expf(l1);
                ssum0 += p0; ssum1 += p1;
                u64 P0 = pk2(p0, p0), P1 = pk2(p1, p1);
                const float4* vp = (const float4*)&Vs[4 * g + j][chalf * 32];
#pragma unroll
                for (int cq = 0; cq < 8; cq++) {
                    V4 vv; vv.f = vp[cq];
                    acc0[2 * cq]     = ffma2(P0, vv.u[0], acc0[2 * cq]);
                    acc0[2 * cq + 1] = ffma2(P0, vv.u[1], acc0[2 * cq + 1]);
                    acc1[2 * cq]     = ffma2(P1, vv.u[0], acc1[2 * cq]);
                    acc1[2 * cq + 1] = ffma2(P1, vv.u[1], acc1[2 * cq + 1]);
                }
            }
        }
        __syncthreads();
    }

    if (chalf == 0) {
        float* ps = g_pssum + ((size_t)ks * BATCH + b) * NPIX + nq;
        ps[0] = ssum0;
        ps[1] = ssum1;
    }
    float* pa = g_pacc + ((size_t)ks * BATCH + b) * CH * NPIX;
#pragma unroll
    for (int i = 0; i < 16; i++) {
        float a0, a1, b0, b1;
        upk2(acc0[i], a0, a1);
        upk2(acc1[i], b0, b1);
        int c = chalf * 32 + 2 * i;
        size_t i00 = (size_t)c * NPIX + nq;
        pa[i00] = a0;
        pa[i00 + NPIX] = a1;
        pa[i00 + 1] = b0;
        pa[i00 + NPIX + 1] = b1;
    }
}

// ---------------- K2s: combine denominators -> scale ----------------
__global__ void k2s_scale(const float* __restrict__ alpha) {
    const int idx = blockIdx.x * 256 + threadIdx.x;  // b*NPIX+n
    if (idx >= BATCH * NPIX) return;
    float s = 0.f;
#pragma unroll
    for (int k = 0; k < KSPLIT; k++) s += g_pssum[(size_t)k * BATCH * NPIX + idx];
    g_scale[idx] = alpha[0] / s;
}

// ---------------- K2r: combine numerators + residual ----------------
__global__ void k2r_reduce(const float* __restrict__ x) {
    const int idx4 = blockIdx.x * 256 + threadIdx.x;      // float4 index
    const int TOT4 = BATCH * CH * NPIX / 4;
    if (idx4 >= TOT4) return;
    const int idx = idx4 * 4;
    const int n = idx & (NPIX - 1);
    const int b = idx / (CH * NPIX);

    float4 a = *(const float4*)&g_pacc[idx];
#pragma unroll
    for (int k = 1; k < KSPLIT; k++) {
        float4 p = *(const float4*)&g_pacc[(size_t)k * BATCH * CH * NPIX + idx];
        a.x += p.x; a.y += p.y; a.z += p.z; a.w += p.w;
    }
    float4 sc = *(const float4*)&g_scale[b * NPIX + n];
    float4 xv = *(const float4*)&x[idx];
    float4 o;
    o.x = fmaf(sc.x, a.x, xv.x);
    o.y = fmaf(sc.y, a.y, xv.y);
    o.z = fmaf(sc.z, a.z, xv.z);
    o.w = fmaf(sc.w, a.w, xv.w);
    *(float4*)&g_xa[idx] = o;
}

// ---------------- K3: CAM Gram matrix partials ----------------
__global__ void k3_att() {
    __shared__ float Xs[64][129];
    const int t = threadIdx.x;
    const int b = blockIdx.x;
    const int s = blockIdx.y;
    const int tx = t & 15, ty = t >> 4;

    float a4[4][4];
#pragma unroll
    for (int i = 0; i < 4; i++)
#pragma unroll
        for (int j = 0; j < 4; j++) a4[i][j] = 0.f;

    for (int chunk = 0; chunk < 2; chunk++) {
        const int n0 = s * 256 + chunk * 128;
        for (int i = t; i < 64 * 128; i += 256) {
            int c = i >> 7, col = i & 127;
            Xs[c][col] = g_xa[(size_t)(b * CH + c) * NPIX + n0 + col];
        }
        __syncthreads();
        for (int nn = 0; nn < 128; nn++) {
            float av[4], bv[4];
#pragma unroll
            for (int i = 0; i < 4; i++) av[i] = Xs[ty * 4 + i][nn];
#pragma unroll
            for (int j = 0; j < 4; j++) bv[j] = Xs[tx * 4 + j][nn];
#pragma unroll
            for (int i = 0; i < 4; i++)
#pragma unroll
                for (int j = 0; j < 4; j++) a4[i][j] = fmaf(av[i], bv[j], a4[i][j]);
        }
        __syncthreads();
    }
#pragma unroll
    for (int i = 0; i < 4; i++)
#pragma unroll
        for (int j = 0; j < 4; j++)
            g_attPart[(((size_t)s * BATCH + b) * CH + ty * 4 + i) * CH + tx * 4 + j] = a4[i][j];
}

// ---------------- K3b: reduce partials + CAM softmax ----------------
__global__ void k3b_softmax() {
    const int c = blockIdx.x;
    const int b = blockIdx.y;
    const int d = threadIdx.x;
    const int lane = d & 31, warp = d >> 5;

    float s = 0.f;
#pragma unroll
    for (int sp = 0; sp < 16; sp++)
        s += g_attPart[(((size_t)sp * BATCH + b) * CH + c) * CH + d];

    float mn = s;
#pragma unroll
    for (int off = 16; off > 0; off >>= 1)
        mn = fminf(mn, __shfl_xor_sync(0xFFFFFFFFu, mn, off));
    __shared__ float sm2[2], ss2[2];
    if (lane == 0) sm2[warp] = mn;
    __syncthreads();
    mn = fminf(sm2[0], sm2[1]);

    float p = __expf(mn - s);
    float ps = p;
#pragma unroll
    for (int off = 16; off > 0; off >>= 1)
        ps += __shfl_xor_sync(0xFFFFFFFFu, ps, off);
    if (lane == 0) ss2[warp] = ps;
    __syncthreads();
    const float inv = 1.f / (ss2[0] + ss2[1]);
    g_attW[((size_t)b * CH + c) * CH + d] = p * inv;
}

// ---------------- K4: CAM apply + beta residual ----------------
__global__ void k4_cam(const float* __restrict__ beta) {
    __shared__ float Xs[64][64];
    __shared__ float Ws[64][64];
    const int t = threadIdx.x;
    const int b = blockIdx.y;
    const int n0 = blockIdx.x * 64;

    for (int i = t; i < 64 * 64; i += 256) {
        int c = i >> 6, col = i & 63;
        Xs[c][col] = g_xa[(size_t)(b * CH + c) * NPIX + n0 + col];
        ((float*)Ws)[i] = g_attW[(size_t)b * CH * CH + i];
    }
    __syncthreads();

    const int tx = t & 7, ty = t >> 3;
    float acc[2][8];
#pragma unroll
    for (int i = 0; i < 2; i++)
#pragma unroll
        for (int j = 0; j < 8; j++) acc[i][j] = 0.f;

    for (int d = 0; d < 64; d++) {
        float w0 = Ws[ty * 2 + 0][d];
        float w1 = Ws[ty * 2 + 1][d];
        float xv[8];
#pragma unroll
        for (int j = 0; j < 8; j++) xv[j] = Xs[d][tx * 8 + j];
#pragma unroll
        for (int j = 0; j < 8; j++) {
            acc[0][j] = fmaf(w0, xv[j], acc[0][j]);
            acc[1][j] = fmaf(w1, xv[j], acc[1][j]);
        }
    }
    const float be = beta[0];
#pragma unroll
    for (int i = 0; i < 2; i++) {
        int c = ty * 2 + i;
#pragma unroll
        for (int j = 0; j < 8; j++) {
            int nn = tx * 8 + j;
            g_xb[(size_t)(b * CH + c) * NPIX + n0 + nn] = fmaf(be, acc[i][j], Xs[c][nn]);
        }
    }
}

// ---------------- K5w: duplicate conv weights to float2 ----------------
__global__ void k5w_dup(const float* __restrict__ cw) {
    int i = blockIdx.x * 256 + threadIdx.x;
    if (i < 128 * 576) {
        float w = cw[i];
        g_cw2[i] = make_float2(w, w);
    }
}

// ---------------- K5: conv3x3 (64->128), f32x2, pad 1 ----------------
__global__ void __launch_bounds__(256) k5_conv(const float* __restrict__ cb) {
    __shared__ float In[4][34][34];
    __shared__ float2 Wt2[4 * 576];
    const int t = threadIdx.x;
    const int tile = blockIdx.x;
    const int ocg = blockIdx.y;
    const int b = blockIdx.z;
    const int h0 = (tile >> 1) * 32;
    const int w0 = (tile & 1) * 32;
    const int tx = t & 15, ty = t >> 4;

    for (int i = t; i < 2304; i += 256) Wt2[i] = g_cw2[(size_t)ocg * 2304 + i];

    u64 acc2[4][2];
#pragma unroll
    for (int o = 0; o < 4; o++) { acc2[o][0] = 0ull; acc2[o][1] = 0ull; }

    for (int cc = 0; cc < 16; cc++) {
        __syncthreads();
        for (int i = t; i < 4 * 34 * 34; i += 256) {
            int ic = i / 1156;
            int rem = i - ic * 1156;
            int r = rem / 34, cl = rem - r * 34;
            int gh = h0 + r - 1, gw = w0 + cl - 1;
            float v = 0.f;
            if (gh >= 0 && gh < 64 && gw >= 0 && gw < 64)
                v = g_xb[(size_t)(b * CH + cc * 4 + ic) * NPIX + gh * 64 + gw];
            In[ic][r][cl] = v;
        }
        __syncthreads();
#pragma unroll
        for (int ic = 0; ic < 4; ic++) {
            u64 xa2[4], xb2[4], xm[4];
#pragma unroll
            for (int dy = 0; dy < 4; dy++) {
                F2 A, Bv;
                A.f  = *(const float2*)&In[ic][ty * 2 + dy][tx * 2];
                Bv.f = *(const float2*)&In[ic][ty * 2 + dy][tx * 2 + 2];
                xa2[dy] = A.u;
                xb2[dy] = Bv.u;
                xm[dy] = pk2(A.f.y, Bv.f.x);
            }
            const int icf = cc * 4 + ic;
#pragma unroll
            for (int o = 0; o < 4; o++) {
                const float2* wp = &Wt2[o * 576 + icf * 9];
#pragma unroll
                for (int ky = 0; ky < 3; ky++)
#pragma unroll
                    for (int kx = 0; kx < 3; kx++) {
                        F2 w; w.f = wp[ky * 3 + kx];
                        const u64* xrow = (kx == 0) ? xa2 : (kx == 1) ? xm : xb2;
                        acc2[o][0] = ffma2(w.u, xrow[ky + 0], acc2[o][0]);
                        acc2[o][1] = ffma2(w.u, xrow[ky + 1], acc2[o][1]);
                    }
            }
        }
    }
#pragma unroll
    for (int o = 0; o < 4; o++) {
        const int oc = ocg * 4 + o;
        const float bs = cb[oc];
#pragma unroll
        for (int a = 0; a < 2; a++) {
            float r0, r1;
            upk2(acc2[o][a], r0, r1);
            int hh = h0 + ty * 2 + a, ww = w0 + tx * 2;
            size_t base = (size_t)(b * 128 + oc) * NPIX + hh * 64 + ww;
            g_conv[base] = r0 + bs;
            g_conv[base + 1] = r1 + bs;
        }
    }
}

// ---------------- K5b: BN stats per channel ----------------
__global__ void k5b_bn(const float* __restrict__ gamma, const float* __restrict__ bbeta) {
    const int oc = blockIdx.x;
    const int t = threadIdx.x;
    float s = 0.f, sq = 0.f;
    for (int i = t; i < BATCH * NPIX; i += 256) {
        int bb = i >> 12, hw = i & 4095;
        float v = g_conv[(size_t)(bb * 128 + oc) * NPIX + hw];
        s += v;
        sq += v * v;
    }
    __shared__ float rs[256], rq[256];
    rs[t] = s; rq[t] = sq;
    __syncthreads();
    for (int st = 128; st > 0; st >>= 1) {
        if (t < st) { rs[t] += rs[t + st]; rq[t] += rq[t + st]; }
        __syncthreads();
    }
    if (t == 0) {
        const float invN = 1.f / (BATCH * NPIX);
        float mean = rs[0] * invN;
        float var = rq[0] * invN - mean * mean;
        float sc = gamma[oc] * rsqrtf(var + 1e-5f);
        g_bnScale[oc] = sc;
        g_bnShift[oc] = bbeta[oc] - mean * sc;
    }
}

// ---------------- K7: BN apply + ReLU + maxpool(2,2, h-pad 1) ----------------
__global__ void k7_pool(float* __restrict__ out) {
    const int idx = blockIdx.x * 256 + threadIdx.x;
    const int TOT = BATCH * 128 * 33 * 32;
    if (idx >= TOT) return;
    int pw = idx & 31;
    int tmp = idx >> 5;
    int ph = tmp % 33; tmp /= 33;
    int oc = tmp & 127;
    int b = tmp >> 7;

    const float sc = g_bnScale[oc], sh = g_bnShift[oc];
    const float* base = g_conv + (size_t)(b * 128 + oc) * NPIX;
    const int w1 = pw * 2;
    const int h1 = ph * 2 - 1;
    float m = -3.4e38f;
#pragma unroll
    for (int k = 0; k < 2; k++) {
        int hh = h1 + k;
        if (hh < 0 || hh >= 64) continue;
        m = fmaxf(m, fmaf(base[hh * 64 + w1], sc, sh));
        m = fmaxf(m, fmaf(base[hh * 64 + w1 + 1], sc, sh));
    }
    out[idx] = fmaxf(m, 0.f);
}

// ---------------- launch ----------------
extern "C" void kernel_launch(void* const* d_in, const int* in_sizes, int n_in,
                              void* d_out, int out_size) {
    const float* x     = (const float*)d_in[0];
    const float* wb    = (const float*)d_in[1];
    const float* bb    = (const float*)d_in[2];
    const float* wc    = (const float*)d_in[3];
    const float* bc    = (const float*)d_in[4];
    const float* wd    = (const float*)d_in[5];
    const float* bd    = (const float*)d_in[6];
    const float* alpha = (const float*)d_in[7];
    const float* beta  = (const float*)d_in[8];
    const float* cw    = (const float*)d_in[9];
    const float* cb    = (const float*)d_in[10];
    const float* gamma = (const float*)d_in[11];
    const float* bbeta = (const float*)d_in[12];
    float* out = (float*)d_out;

    k5w_dup<<<(128 * 576 + 255) / 256, 256>>>(cw);
    k1_proj<<<dim3(16, 5, 8), 256>>>(x, wb, bb, wc, bc, wd, bd);
    k1t_transpose<<<dim3(64, 8), 256>>>();
    k2_pam<<<dim3(32, KSPLIT, 8), 128>>>();
    k2s_scale<<<(BATCH * NPIX + 255) / 256, 256>>>(alpha);
    k2r_reduce<<<(BATCH * CH * NPIX / 4 + 255) / 256, 256>>>(x);
    k3_att<<<dim3(8, 16), 256>>>();
    k3b_softmax<<<dim3(64, 8), 64>>>();
    k4_cam<<<dim3(64, 8), 256>>>(beta);
    k5_conv<<<dim3(4, 32, 8), 256>>>(cb);
    k5b_bn<<<128, 256>>>(gamma, bbeta);
    const int tot = BATCH * 128 * 33 * 32;
    k7_pool<<<(tot + 255) / 256, 256>>>(out);
}